// round 7
// baseline (speedup 1.0000x reference)
#include <cuda_runtime.h>
#include <math.h>

// Problem dims (fixed by the reference)
#define BB   2
#define SEQ  2048
#define DIM  768
#define NH   12
#define DHD  64
#define FFD  3072
#define PDIM 64
#define PDPAD 128
#define NROW (BB*SEQ)      // 4096

#define STAGES 3
#define BK     32
#define LDRW   36          // padded row length in 4-byte words
#define SMEM_DYN (STAGES*128*LDRW*4*2)   // 110592 bytes

// ---------------- scratch (device globals; no cudaMalloc allowed) ----------
__device__ __align__(16) float g_xn[NROW*DIM];
__device__ __align__(16) float g_xnT[NROW*DIM];                   // [B][D][S]
__device__ __align__(16) float g_qk[NROW*2*DIM];
__device__ __align__(16) float g_phw[PDPAD*DIM];
__device__ __align__(16) float g_phase[NROW*PDPAD];
__device__ __align__(16) float g_scores[(size_t)BB*NH*SEQ*SEQ];
__device__              float g_ssum[BB*NH*SEQ];
__device__ __align__(16) float g_pc[(size_t)BB*SEQ*SEQ];
__device__ __align__(16) float g_blend[(size_t)BB*SEQ*SEQ];
__device__              float g_rowsum[BB*SEQ];
__device__ __align__(16) float g_xmid[NROW*DIM];
__device__ __align__(16) float g_x2[NROW*DIM];
__device__ __align__(16) float g_hbuf[NROW*FFD];
// tf32-rounded weight copies
__device__ __align__(16) float g_inw[2*DIM*DIM];
__device__ __align__(16) float g_w1[FFD*DIM];
__device__ __align__(16) float g_w2[DIM*FFD];

// ---------------- helpers ----------------------------------------------------
__device__ __forceinline__ float warpReduceSum(float v) {
#pragma unroll
    for (int o = 16; o > 0; o >>= 1) v += __shfl_xor_sync(0xffffffffu, v, o);
    return v;
}
__device__ __forceinline__ float blockReduceSum256(float v, float* sm) {
    v = warpReduceSum(v);
    if ((threadIdx.x & 31) == 0) sm[threadIdx.x >> 5] = v;
    __syncthreads();
    if (threadIdx.x < 32) {
        float t = (threadIdx.x < 8) ? sm[threadIdx.x] : 0.0f;
        t = warpReduceSum(t);
        if (threadIdx.x == 0) sm[0] = t;
    }
    __syncthreads();
    float r = sm[0];
    __syncthreads();
    return r;
}

// Fast exp on the FMA pipe. Max rel err ~3e-6.
__device__ __forceinline__ float fast_exp(float x) {
    x = fmaxf(x, -87.0f);
    float y  = x * 1.4426950408889634f;
    float z  = y + 12582912.0f;
    float nf = z - 12582912.0f;
    float f  = y - nf;
    float p  = 1.3333558146e-3f;
    p = fmaf(p, f, 9.6181291076e-3f);
    p = fmaf(p, f, 5.5504108665e-2f);
    p = fmaf(p, f, 2.4022650696e-1f);
    p = fmaf(p, f, 6.9314718056e-1f);
    p = fmaf(p, f, 1.0f);
    unsigned sb = ((unsigned)__float_as_int(z) + (unsigned)(127 - 0x4B400000)) << 23;
    return p * __int_as_float(sb);
}

// round fp32 -> tf32 (round-to-nearest), returned as fp32 with low bits zero
__device__ __forceinline__ float round_tf32(float x) {
    unsigned u;
    asm("cvt.rna.tf32.f32 %0, %1;" : "=r"(u) : "f"(x));
    return __uint_as_float(u);
}

__device__ __forceinline__ void mma_tf32(float* c, const unsigned* a, const unsigned* b) {
    asm("mma.sync.aligned.m16n8k8.row.col.f32.tf32.tf32.f32 "
        "{%0,%1,%2,%3}, {%4,%5,%6,%7}, {%8,%9}, {%0,%1,%2,%3};"
        : "+f"(c[0]), "+f"(c[1]), "+f"(c[2]), "+f"(c[3])
        : "r"(a[0]), "r"(a[1]), "r"(a[2]), "r"(a[3]), "r"(b[0]), "r"(b[1]));
}
__device__ __forceinline__ void ldsm_x4(unsigned& r0, unsigned& r1,
                                        unsigned& r2, unsigned& r3, unsigned addr) {
    asm volatile("ldmatrix.sync.aligned.m8n8.x4.shared.b16 {%0,%1,%2,%3}, [%4];"
        : "=r"(r0), "=r"(r1), "=r"(r2), "=r"(r3) : "r"(addr));
}
__device__ __forceinline__ unsigned smem_u32(const void* p) {
    unsigned a;
    asm("{ .reg .u64 t; cvta.to.shared.u64 t, %1; cvt.u32.u64 %0, t; }"
        : "=r"(a) : "l"(p));
    return a;
}
__device__ __forceinline__ void cp_async16(unsigned dst, const void* src) {
    asm volatile("cp.async.cg.shared.global [%0], [%1], 16;" :: "r"(dst), "l"(src));
}

// ---------------- LayerNorm (tf32-rounded output) ----------------------------
__global__ void __launch_bounds__(256) ln_kernel(
    const float* __restrict__ x, const float* __restrict__ w,
    const float* __restrict__ b, float* __restrict__ o)
{
    __shared__ float sm[8];
    const float* xr = x + (size_t)blockIdx.x * DIM;
    int t = threadIdx.x;
    float v0 = xr[t], v1 = xr[t + 256], v2 = xr[t + 512];
    float mean = blockReduceSum256(v0 + v1 + v2, sm) * (1.0f / DIM);
    float d0 = v0 - mean, d1 = v1 - mean, d2 = v2 - mean;
    float var = blockReduceSum256(d0*d0 + d1*d1 + d2*d2, sm) * (1.0f / DIM);
    float r = rsqrtf(var + 1e-5f);
    float* orow = o + (size_t)blockIdx.x * DIM;
    orow[t      ] = round_tf32(d0 * r * w[t      ] + b[t      ]);
    orow[t + 256] = round_tf32(d1 * r * w[t + 256] + b[t + 256]);
    orow[t + 512] = round_tf32(d2 * r * w[t + 512] + b[t + 512]);
}

__global__ void __launch_bounds__(256) zero_kernel(float* __restrict__ p, int n) {
    int i = blockIdx.x * 256 + threadIdx.x;
    if (i < n) p[i] = 0.0f;
}

// copy with tf32 round-to-nearest
__global__ void __launch_bounds__(256) round_copy_kernel(
    const float* __restrict__ in, float* __restrict__ o, int n)
{
    int i = blockIdx.x * 256 + threadIdx.x;
    if (i < n) o[i] = round_tf32(in[i]);
}

// pad phase_w [64,768] -> [128,768] with zeros, tf32-rounded
__global__ void __launch_bounds__(256) pad_phw_kernel(
    const float* __restrict__ w, float* __restrict__ o)
{
    int i = blockIdx.x * 256 + threadIdx.x;
    if (i < PDPAD * DIM) o[i] = (i < PDIM * DIM) ? round_tf32(w[i]) : 0.0f;
}

// transpose per batch: in [SEQ][DIM] -> out [DIM][SEQ]
__global__ void __launch_bounds__(256) transpose_kernel(
    const float* __restrict__ in, float* __restrict__ out)
{
    __shared__ float t[32][33];
    int b = blockIdx.z;
    const float* ib = in + (size_t)b * SEQ * DIM;
    float* ob = out + (size_t)b * SEQ * DIM;
    int tx = threadIdx.x & 31, ty = threadIdx.x >> 5;
    int sbase = blockIdx.x * 32;
    int dbase = blockIdx.y * 32;
#pragma unroll
    for (int i = 0; i < 32; i += 8)
        t[ty + i][tx] = ib[(size_t)(sbase + ty + i) * DIM + dbase + tx];
    __syncthreads();
#pragma unroll
    for (int i = 0; i < 32; i += 8)
        ob[(size_t)(dbase + ty + i) * SEQ + sbase + tx] = t[tx][ty + i];
}

// ============================================================================
// tf32 tensor-core GEMM: 128x128x32 CTA tile, 8 warps (2x4), warp 64x32,
// mma.sync m16n8k8, 3-stage cp.async pipeline, ldmatrix.x4 fragment loads.
// B is always row-major [N,K]: C = A @ B^T. Inputs must be tf32-pre-rounded.
// EPI: 1=+bias(rna), 2=tanh(rna), 3=bias+GELU(rna), 4=bias+residual,
//      5=row-divide(rowsum)+residual, 6=exp(scale*v)+atomic rowsum,
//      7=exp(a2*v + a2), a2 = 0.5*alpha
// ============================================================================
template<int EPI>
__global__ void __launch_bounds__(256, 2) tgemm(
    const float* __restrict__ A, const float* __restrict__ Bm,
    float* __restrict__ C,
    int M, int N, int K, int lda, int ldb, int ldc,
    int zdiv,
    long as1, long as2, long bs1, long bs2, long cs1, long cs2,
    float scale,
    const float* __restrict__ bias,
    const float* __restrict__ res, long ress1,
    const float* __restrict__ rsum, long rsums1,
    const float* __restrict__ alphap,
    float* __restrict__ ssum)
{
    extern __shared__ unsigned sh[];
    unsigned* Asb = sh;                               // [STAGES][128][LDRW]
    unsigned* Bsb = sh + STAGES * 128 * LDRW;
    const unsigned STAGE_BYTES = 128 * LDRW * 4;

    int z = blockIdx.z;
    int z1 = z / zdiv, z2 = z - z1 * zdiv;
    A  += z1 * as1 + z2 * as2;
    Bm += z1 * bs1 + z2 * bs2;
    C  += z1 * cs1 + z2 * cs2;
    if (EPI == 4 || EPI == 5) res  += z1 * ress1;
    if (EPI == 5)             rsum += z1 * rsums1;
    if (EPI == 6)             ssum += (size_t)z * M;

    int tid  = threadIdx.x;
    int lane = tid & 31;
    int wid  = tid >> 5;
    int wm   = (wid & 1) * 64;
    int wn   = (wid >> 1) * 32;
    int g    = lane >> 2;
    int tg   = lane & 3;
    int bm = blockIdx.x * 128, bn = blockIdx.y * 128;

    float acc[4][4][4];
#pragma unroll
    for (int i = 0; i < 4; i++)
#pragma unroll
        for (int j = 0; j < 4; j++)
#pragma unroll
            for (int r = 0; r < 4; r++) acc[i][j][r] = 0.0f;

    const float* Ab = A + (size_t)bm * lda;
    const float* Bb = Bm + (size_t)bn * ldb;

    // cp.async staging: thread -> row tid/2, float col (tid&1)*16, 4x16B each
    int r0 = tid >> 1;
    int cc = (tid & 1) << 4;
    unsigned asBase = smem_u32(Asb);
    unsigned bsBase = smem_u32(Bsb);
    unsigned aDst = asBase + (r0 * LDRW + cc) * 4;
    unsigned bDst = bsBase + (r0 * LDRW + cc) * 4;
    const float* aSrc = Ab + (size_t)r0 * lda + cc;
    const float* bSrc = Bb + (size_t)r0 * ldb + cc;

    // ldmatrix per-lane addresses (stage 0, ks 0)
    int mi = lane >> 3, lr = lane & 7;
    unsigned aAddr[4], bAddr[2];
#pragma unroll
    for (int mt = 0; mt < 4; mt++)
        aAddr[mt] = asBase + (((wm + mt * 16 + (mi & 1) * 8 + lr) * LDRW) + (mi >> 1) * 4) * 4;
#pragma unroll
    for (int p = 0; p < 2; p++)
        bAddr[p] = bsBase + (((wn + (p * 2 + (mi >> 1)) * 8 + lr) * LDRW) + (mi & 1) * 4) * 4;

    auto stage_load = [&](int st, int k0) {
        if (k0 < K) {
            unsigned so = st * STAGE_BYTES;
#pragma unroll
            for (int q = 0; q < 4; q++) {
                cp_async16(aDst + so + q * 16, aSrc + k0 + q * 4);
                cp_async16(bDst + so + q * 16, bSrc + k0 + q * 4);
            }
        }
        asm volatile("cp.async.commit_group;");
    };

    stage_load(0, 0);
    stage_load(1, BK);

    int s = 0;
    for (int k0 = 0; k0 < K; k0 += BK) {
        asm volatile("cp.async.wait_group 1;");
        __syncthreads();
        int s2 = s + 2; if (s2 >= STAGES) s2 -= STAGES;
        stage_load(s2, k0 + 2 * BK);

        unsigned so = s * STAGE_BYTES;
#pragma unroll
        for (int ks = 0; ks < 4; ks++) {
            unsigned kofs = so + ks * 32;     // 8 words per k-step
            unsigned afr[4][4], bfr[4][2];
#pragma unroll
            for (int mt = 0; mt < 4; mt++)
                ldsm_x4(afr[mt][0], afr[mt][1], afr[mt][2], afr[mt][3],
                        aAddr[mt] + kofs);
            ldsm_x4(bfr[0][0], bfr[0][1], bfr[1][0], bfr[1][1], bAddr[0] + kofs);
            ldsm_x4(bfr[2][0], bfr[2][1], bfr[3][0], bfr[3][1], bAddr[1] + kofs);
#pragma unroll
            for (int mt = 0; mt < 4; mt++)
#pragma unroll
                for (int nt = 0; nt < 4; nt++)
                    mma_tf32(acc[mt][nt], afr[mt], bfr[nt]);
        }
        if (++s >= STAGES) s = 0;
    }

    // ---------------- epilogue ----------------
    float a2v = 0.0f;
    if (EPI == 7) a2v = 0.5f * (*alphap);

#pragma unroll
    for (int mt = 0; mt < 4; mt++) {
#pragma unroll
        for (int half = 0; half < 2; half++) {
            int m = bm + wm + mt * 16 + g + half * 8;
            float rinv = 0.0f;
            if (EPI == 5) rinv = 1.0f / rsum[m];
            float rs = 0.0f;
#pragma unroll
            for (int nt = 0; nt < 4; nt++) {
                int c = bn + wn + nt * 8 + tg * 2;
                float v0 = acc[mt][nt][half * 2];
                float v1 = acc[mt][nt][half * 2 + 1];
                if (EPI == 1) { v0 = round_tf32(v0 + bias[c]); v1 = round_tf32(v1 + bias[c + 1]); }
                if (EPI == 2) { v0 = round_tf32(tanhf(v0)); v1 = round_tf32(tanhf(v1)); }
                if (EPI == 3) {
                    v0 += bias[c]; v1 += bias[c + 1];
                    v0 = round_tf32(0.5f * v0 * (1.0f + erff(v0 * 0.70710678118654752f)));
                    v1 = round_tf32(0.5f * v1 * (1.0f + erff(v1 * 0.70710678118654752f)));
                }
                if (EPI == 4) {
                    const float2 rr = *(const float2*)(res + (size_t)m * ldc + c);
                    v0 += bias[c] + rr.x; v1 += bias[c + 1] + rr.y;
                }
                if (EPI == 5) {
                    const float2 rr = *(const float2*)(res + (size_t)m * ldc + c);
                    v0 = v0 * rinv + rr.x; v1 = v1 * rinv + rr.y;
                }
                if (EPI == 6) { v0 = fast_exp(v0 * scale); v1 = fast_exp(v1 * scale); }
                if (EPI == 7) { v0 = fast_exp(fmaf(v0, a2v, a2v)); v1 = fast_exp(fmaf(v1, a2v, a2v)); }
                if (EPI == 6) rs += v0 + v1;
                float2 o; o.x = v0; o.y = v1;
                *(float2*)(C + (size_t)m * ldc + c) = o;
            }
            if (EPI == 6) {
                rs += __shfl_xor_sync(0xffffffffu, rs, 1);
                rs += __shfl_xor_sync(0xffffffffu, rs, 2);
                if (tg == 0) atomicAdd(&ssum[m], rs);
            }
        }
    }
}

// --------- blend: u = (mean_h softmax_h + 1e-6) * pcexp; rowsum (float4) ----
__global__ void __launch_bounds__(256) blend_kernel(
    const float* __restrict__ scoresE, const float* __restrict__ ssum,
    const float* __restrict__ pcexp, float* __restrict__ blend,
    float* __restrict__ rowsum)
{
    __shared__ float sm[8];
    __shared__ float sinvl[NH];
    int b = blockIdx.x / SEQ;
    int i = blockIdx.x - b * SEQ;
    if (threadIdx.x < NH)
        sinvl[threadIdx.x] = 1.0f / (ssum[(b * NH + threadIdx.x) * SEQ + i] * (float)NH);
    __syncthreads();

    const float* ebase = scoresE + ((size_t)(b * NH) * SEQ + (size_t)i) * SEQ;
    const float* prow  = pcexp + ((size_t)b * SEQ + i) * SEQ;
    float*       brow  = blend + ((size_t)b * SEQ + i) * SEQ;

    float lsum = 0.0f;
    for (int j = threadIdx.x * 4; j < SEQ; j += 1024) {
        float4 w = {1e-6f, 1e-6f, 1e-6f, 1e-6f};
#pragma unroll
        for (int h = 0; h < NH; h++) {
            const float4 e = *(const float4*)(ebase + (size_t)h * SEQ * SEQ + j);
            float sl = sinvl[h];
            w.x = fmaf(e.x, sl, w.x); w.y = fmaf(e.y, sl, w.y);
            w.z = fmaf(e.z, sl, w.z); w.w = fmaf(e.w, sl, w.w);
        }
        const float4 p = *(const float4*)(prow + j);
        float4 u;
        u.x = round_tf32(w.x * p.x); u.y = round_tf32(w.y * p.y);
        u.z = round_tf32(w.z * p.z); u.w = round_tf32(w.w * p.w);
        *(float4*)(brow + j) = u;
        lsum += u.x + u.y + u.z + u.w;
    }
    lsum = blockReduceSum256(lsum, sm);
    if (threadIdx.x == 0) rowsum[blockIdx.x] = lsum;
}

// ---------------------------------------------------------------------------
extern "C" void kernel_launch(void* const* d_in, const int* in_sizes, int n_in,
                              void* d_out, int out_size)
{
    const float* x        = (const float*)d_in[0];
    const float* ln1_w    = (const float*)d_in[1];
    const float* ln1_b    = (const float*)d_in[2];
    const float* in_w     = (const float*)d_in[3];
    const float* in_b     = (const float*)d_in[4];
    const float* phase_w  = (const float*)d_in[5];
    const float* alpha    = (const float*)d_in[6];
    const float* ff_w1    = (const float*)d_in[7];
    const float* ff_b1    = (const float*)d_in[8];
    const float* ff_w2    = (const float*)d_in[9];
    const float* ff_b2    = (const float*)d_in[10];
    const float* ln2_w    = (const float*)d_in[11];
    const float* ln2_b    = (const float*)d_in[12];
    float* out            = (float*)d_out;

    float *xn, *xnT, *qk, *phw, *phase, *scores, *ssum, *pcv, *blend, *rowsum,
          *xmid, *x2, *hbuf, *inw, *w1, *w2;
    cudaGetSymbolAddress((void**)&xn,     g_xn);
    cudaGetSymbolAddress((void**)&xnT,    g_xnT);
    cudaGetSymbolAddress((void**)&qk,     g_qk);
    cudaGetSymbolAddress((void**)&phw,    g_phw);
    cudaGetSymbolAddress((void**)&phase,  g_phase);
    cudaGetSymbolAddress((void**)&scores, g_scores);
    cudaGetSymbolAddress((void**)&ssum,   g_ssum);
    cudaGetSymbolAddress((void**)&pcv,    g_pc);
    cudaGetSymbolAddress((void**)&blend,  g_blend);
    cudaGetSymbolAddress((void**)&rowsum, g_rowsum);
    cudaGetSymbolAddress((void**)&xmid,   g_xmid);
    cudaGetSymbolAddress((void**)&x2,     g_x2);
    cudaGetSymbolAddress((void**)&hbuf,   g_hbuf);
    cudaGetSymbolAddress((void**)&inw,    g_inw);
    cudaGetSymbolAddress((void**)&w1,     g_w1);
    cudaGetSymbolAddress((void**)&w2,     g_w2);

    cudaFuncSetAttribute(tgemm<1>, cudaFuncAttributeMaxDynamicSharedMemorySize, SMEM_DYN);
    cudaFuncSetAttribute(tgemm<2>, cudaFuncAttributeMaxDynamicSharedMemorySize, SMEM_DYN);
    cudaFuncSetAttribute(tgemm<3>, cudaFuncAttributeMaxDynamicSharedMemorySize, SMEM_DYN);
    cudaFuncSetAttribute(tgemm<4>, cudaFuncAttributeMaxDynamicSharedMemorySize, SMEM_DYN);
    cudaFuncSetAttribute(tgemm<5>, cudaFuncAttributeMaxDynamicSharedMemorySize, SMEM_DYN);
    cudaFuncSetAttribute(tgemm<6>, cudaFuncAttributeMaxDynamicSharedMemorySize, SMEM_DYN);
    cudaFuncSetAttribute(tgemm<7>, cudaFuncAttributeMaxDynamicSharedMemorySize, SMEM_DYN);

    // 0) tf32 round-to-nearest weight copies (makes cp.async truncation lossless)
    round_copy_kernel<<<(2*DIM*DIM + 255)/256, 256>>>(in_w, inw, 2*DIM*DIM);
    round_copy_kernel<<<(FFD*DIM + 255)/256, 256>>>(ff_w1, w1, FFD*DIM);
    round_copy_kernel<<<(DIM*FFD + 255)/256, 256>>>(ff_w2, w2, DIM*FFD);

    // 1) xn = LN1(x) (rna); xnT; zero per-head sums; pad+round phase_w
    ln_kernel<<<NROW, 256>>>(x, ln1_w, ln1_b, xn);
    zero_kernel<<<(BB*NH*SEQ + 255)/256, 256>>>(ssum, BB*NH*SEQ);
    pad_phw_kernel<<<(PDPAD*DIM + 255)/256, 256>>>(phase_w, phw);
    transpose_kernel<<<dim3(SEQ/32, DIM/32, BB), 256>>>(xn, xnT);

    // 2) qk = xn @ W[0:1536]^T + b (rna)     [4096, 1536]
    tgemm<1><<<dim3(NROW/128, 1536/128, 1), 256, SMEM_DYN>>>(
        xn, inw, qk, NROW, 2*DIM, DIM, DIM, DIM, 2*DIM,
        1, 0,0, 0,0, 0,0, 1.0f, in_b, nullptr, 0, nullptr, 0, nullptr, nullptr);

    // 3) phase = tanh(xn @ phw^T) (rna)      [4096, 128] (cols 64..127 = 0)
    tgemm<2><<<dim3(NROW/128, 1, 1), 256, SMEM_DYN>>>(
        xn, phw, phase, NROW, PDPAD, DIM, DIM, DIM, PDPAD,
        1, 0,0, 0,0, 0,0, 1.0f, nullptr, nullptr, 0, nullptr, 0, nullptr, nullptr);

    // 4) scores e = exp(0.125 * q@k^T) + atomic row sums    24 x [2048,2048]
    tgemm<6><<<dim3(SEQ/128, SEQ/128, BB*NH), 256, SMEM_DYN>>>(
        qk, qk + DIM, scores, SEQ, SEQ, DHD, 2*DIM, 2*DIM, SEQ,
        NH, (long)SEQ*2*DIM, (long)DHD, (long)SEQ*2*DIM, (long)DHD,
            (long)NH*SEQ*SEQ, (long)SEQ*SEQ,
        0.125f, nullptr, nullptr, 0, nullptr, 0, nullptr, ssum);

    // 5) pcexp = exp(0.5*alpha*(phase@phase^T) + 0.5*alpha)  2 x [2048,2048]
    tgemm<7><<<dim3(SEQ/128, SEQ/128, BB), 256, SMEM_DYN>>>(
        phase, phase, pcv, SEQ, SEQ, PDPAD, PDPAD, PDPAD, SEQ,
        1, (long)SEQ*PDPAD, 0, (long)SEQ*PDPAD, 0, (long)SEQ*SEQ, 0,
        1.0f, nullptr, nullptr, 0, nullptr, 0, alpha, nullptr);

    // 6) blend weights + row sums
    blend_kernel<<<BB*SEQ, 256>>>(scores, ssum, pcv, blend, rowsum);

    // 7) xmid = x + (blend/rowsum) @ xnT^T    2 x [2048, 768]
    tgemm<5><<<dim3(SEQ/128, DIM/128, BB), 256, SMEM_DYN>>>(
        blend, xnT, xmid, SEQ, DIM, SEQ, SEQ, SEQ, DIM,
        1, (long)SEQ*SEQ, 0, (long)DIM*SEQ, 0, (long)SEQ*DIM, 0,
        1.0f, nullptr, x, (long)SEQ*DIM, rowsum, (long)SEQ, nullptr, nullptr);

    // 8) x2 = LN2(xmid) (rna)
    ln_kernel<<<NROW, 256>>>(xmid, ln2_w, ln2_b, x2);

    // 9) h = gelu(x2 @ ff_w1^T + b1) (rna)    [4096, 3072]
    tgemm<3><<<dim3(NROW/128, FFD/128, 1), 256, SMEM_DYN>>>(
        x2, w1, hbuf, NROW, FFD, DIM, DIM, DIM, FFD,
        1, 0,0, 0,0, 0,0, 1.0f, ff_b1, nullptr, 0, nullptr, 0, nullptr, nullptr);

    // 10) out = xmid + h @ ff_w2^T + b2       [4096, 768]
    tgemm<4><<<dim3(NROW/128, DIM/128, 1), 256, SMEM_DYN>>>(
        hbuf, w2, out, NROW, DIM, FFD, FFD, FFD, DIM,
        1, 0,0, 0,0, 0,0, 1.0f, ff_b2, xmid, 0, nullptr, 0, nullptr, nullptr);

    (void)in_sizes; (void)n_in; (void)out_size;
}

// round 9
// speedup vs baseline: 1.7889x; 1.7889x over previous
#include <cuda_runtime.h>
#include <cuda_fp16.h>
#include <math.h>

// Problem dims (fixed by the reference)
#define BB   2
#define SEQ  2048
#define DIM  768
#define NH   12
#define DHD  64
#define FFD  3072
#define PDIM 64
#define PDPAD 128
#define NROW (BB*SEQ)      // 4096

#define STAGES 3
#define BKH    32                        // k-tile in halves
#define LDRH   40                        // padded row length in halves (80 B)
#define OPSTG  (128*LDRH*2)              // 10240 B per operand per stage
#define STAGE_BYTES (2*OPSTG)            // 20480
#define SMEM_DYN (STAGES*STAGE_BYTES)    // 61440

// ---------------- scratch (device globals; no cudaMalloc allowed) ----------
__device__ __align__(16) __half g_xn[NROW*DIM];
__device__ __align__(16) __half g_xnT[NROW*DIM];                  // [B][D][S]
__device__ __align__(16) __half g_qk[NROW*2*DIM];
__device__ __align__(16) __half g_phw[PDPAD*DIM];
__device__ __align__(16) __half g_phase[NROW*PDPAD];
__device__ __align__(16) __half g_scores[(size_t)BB*NH*SEQ*SEQ]; // exp(s/8) fp16
__device__              float  g_ssum[BB*NH*SEQ];
__device__ __align__(16) __half g_pc[(size_t)BB*SEQ*SEQ];        // exp(a*(pc+1)/2)
__device__ __align__(16) __half g_blend[(size_t)BB*SEQ*SEQ];
__device__              float  g_rowsum[BB*SEQ];
__device__ __align__(16) float  g_xmid[NROW*DIM];                // residual: fp32
__device__ __align__(16) __half g_x2[NROW*DIM];
__device__ __align__(16) __half g_hbuf[NROW*FFD];
// fp16-rounded weight copies
__device__ __align__(16) __half g_inw[2*DIM*DIM];
__device__ __align__(16) __half g_w1[FFD*DIM];
__device__ __align__(16) __half g_w2[DIM*FFD];

// ---------------- helpers ----------------------------------------------------
__device__ __forceinline__ float warpReduceSum(float v) {
#pragma unroll
    for (int o = 16; o > 0; o >>= 1) v += __shfl_xor_sync(0xffffffffu, v, o);
    return v;
}
__device__ __forceinline__ float blockReduceSum256(float v, float* sm) {
    v = warpReduceSum(v);
    if ((threadIdx.x & 31) == 0) sm[threadIdx.x >> 5] = v;
    __syncthreads();
    if (threadIdx.x < 32) {
        float t = (threadIdx.x < 8) ? sm[threadIdx.x] : 0.0f;
        t = warpReduceSum(t);
        if (threadIdx.x == 0) sm[0] = t;
    }
    __syncthreads();
    float r = sm[0];
    __syncthreads();
    return r;
}

// Fast exp on the FMA pipe. Max rel err ~3e-6.
__device__ __forceinline__ float fast_exp(float x) {
    x = fmaxf(x, -87.0f);
    float y  = x * 1.4426950408889634f;
    float z  = y + 12582912.0f;
    float nf = z - 12582912.0f;
    float f  = y - nf;
    float p  = 1.3333558146e-3f;
    p = fmaf(p, f, 9.6181291076e-3f);
    p = fmaf(p, f, 5.5504108665e-2f);
    p = fmaf(p, f, 2.4022650696e-1f);
    p = fmaf(p, f, 6.9314718056e-1f);
    p = fmaf(p, f, 1.0f);
    unsigned sb = ((unsigned)__float_as_int(z) + (unsigned)(127 - 0x4B400000)) << 23;
    return p * __int_as_float(sb);
}

__device__ __forceinline__ unsigned smem_u32(const void* p) {
    unsigned a;
    asm("{ .reg .u64 t; cvta.to.shared.u64 t, %1; cvt.u32.u64 %0, t; }"
        : "=r"(a) : "l"(p));
    return a;
}
__device__ __forceinline__ void cp_async16(unsigned dst, const void* src) {
    asm volatile("cp.async.cg.shared.global [%0], [%1], 16;" :: "r"(dst), "l"(src));
}
__device__ __forceinline__ void ldsm_x4(unsigned& r0, unsigned& r1,
                                        unsigned& r2, unsigned& r3, unsigned addr) {
    asm volatile("ldmatrix.sync.aligned.m8n8.x4.shared.b16 {%0,%1,%2,%3}, [%4];"
        : "=r"(r0), "=r"(r1), "=r"(r2), "=r"(r3) : "r"(addr));
}
__device__ __forceinline__ void mma_f16(float* c, const unsigned* a, const unsigned* b) {
    asm("mma.sync.aligned.m16n8k16.row.col.f32.f16.f16.f32 "
        "{%0,%1,%2,%3}, {%4,%5,%6,%7}, {%8,%9}, {%0,%1,%2,%3};"
        : "+f"(c[0]), "+f"(c[1]), "+f"(c[2]), "+f"(c[3])
        : "r"(a[0]), "r"(a[1]), "r"(a[2]), "r"(a[3]), "r"(b[0]), "r"(b[1]));
}

// ---------------- LayerNorm: fp32 in, fp16 out -------------------------------
__global__ void __launch_bounds__(256) ln_kernel(
    const float* __restrict__ x, const float* __restrict__ w,
    const float* __restrict__ b, __half* __restrict__ o)
{
    __shared__ float sm[8];
    const float* xr = x + (size_t)blockIdx.x * DIM;
    int t = threadIdx.x;
    float v0 = xr[t], v1 = xr[t + 256], v2 = xr[t + 512];
    float mean = blockReduceSum256(v0 + v1 + v2, sm) * (1.0f / DIM);
    float d0 = v0 - mean, d1 = v1 - mean, d2 = v2 - mean;
    float var = blockReduceSum256(d0*d0 + d1*d1 + d2*d2, sm) * (1.0f / DIM);
    float r = rsqrtf(var + 1e-5f);
    __half* orow = o + (size_t)blockIdx.x * DIM;
    orow[t      ] = __float2half_rn(d0 * r * w[t      ] + b[t      ]);
    orow[t + 256] = __float2half_rn(d1 * r * w[t + 256] + b[t + 256]);
    orow[t + 512] = __float2half_rn(d2 * r * w[t + 512] + b[t + 512]);
}

__global__ void __launch_bounds__(256) zero_kernel(float* __restrict__ p, int n) {
    int i = blockIdx.x * 256 + threadIdx.x;
    if (i < n) p[i] = 0.0f;
}

__global__ void __launch_bounds__(256) half_copy_kernel(
    const float* __restrict__ in, __half* __restrict__ o, int n)
{
    int i = blockIdx.x * 256 + threadIdx.x;
    if (i < n) o[i] = __float2half_rn(in[i]);
}

// pad phase_w [64,768] -> [128,768] with zeros, fp16
__global__ void __launch_bounds__(256) pad_phw_kernel(
    const float* __restrict__ w, __half* __restrict__ o)
{
    int i = blockIdx.x * 256 + threadIdx.x;
    if (i < PDPAD * DIM) o[i] = __float2half_rn((i < PDIM * DIM) ? w[i] : 0.0f);
}

// transpose per batch: in [SEQ][DIM] -> out [DIM][SEQ]  (fp16)
__global__ void __launch_bounds__(256) transpose_kernel(
    const __half* __restrict__ in, __half* __restrict__ out)
{
    __shared__ __half t[32][33];
    int b = blockIdx.z;
    const __half* ib = in + (size_t)b * SEQ * DIM;
    __half* ob = out + (size_t)b * SEQ * DIM;
    int tx = threadIdx.x & 31, ty = threadIdx.x >> 5;
    int sbase = blockIdx.x * 32;
    int dbase = blockIdx.y * 32;
#pragma unroll
    for (int i = 0; i < 32; i += 8)
        t[ty + i][tx] = ib[(size_t)(sbase + ty + i) * DIM + dbase + tx];
    __syncthreads();
#pragma unroll
    for (int i = 0; i < 32; i += 8)
        ob[(size_t)(dbase + ty + i) * SEQ + sbase + tx] = t[tx][ty + i];
}

// ============================================================================
// fp16 tensor-core GEMM: 128x128x32 CTA tile, 8 warps (2x4), warp 64x32,
// mma.sync m16n8k16 (f32 accum), 3-stage cp.async pipeline, ldmatrix.x4.
// A [M,K] half row-major, B [N,K] half row-major: C = A @ B^T.
// EPI: 1=+bias->h, 2=tanh->h, 3=bias+GELU->h, 4=bias+residual->f,
//      5=row-divide(rowsum)+residual->f, 6=exp(scale*v)->h + atomic rowsum,
//      7=exp(a2*v + a2)->h, a2 = 0.5*alpha
// ============================================================================
template<int EPI> struct OutT { using T = __half; };
template<> struct OutT<4> { using T = float; };
template<> struct OutT<5> { using T = float; };

template<int EPI>
__global__ void __launch_bounds__(256, 2) tgemm(
    const __half* __restrict__ A, const __half* __restrict__ Bm,
    typename OutT<EPI>::T* __restrict__ C,
    int M, int N, int K, int lda, int ldb, int ldc,
    int zdiv,
    long as1, long as2, long bs1, long bs2, long cs1, long cs2,
    float scale,
    const float* __restrict__ bias,
    const float* __restrict__ res, long ress1,
    const float* __restrict__ rsum, long rsums1,
    const float* __restrict__ alphap,
    float* __restrict__ ssum)
{
    constexpr bool OUTH = (EPI != 4 && EPI != 5);
    extern __shared__ char sh[];

    int z = blockIdx.z;
    int z1 = z / zdiv, z2 = z - z1 * zdiv;
    A  += z1 * as1 + z2 * as2;
    Bm += z1 * bs1 + z2 * bs2;
    C  += z1 * cs1 + z2 * cs2;
    if (EPI == 4 || EPI == 5) res  += z1 * ress1;
    if (EPI == 5)             rsum += z1 * rsums1;
    if (EPI == 6)             ssum += (size_t)z * M;

    int tid  = threadIdx.x;
    int lane = tid & 31;
    int wid  = tid >> 5;
    int wm   = (wid & 1) * 64;
    int wn   = (wid >> 1) * 32;
    int g    = lane >> 2;
    int tg   = lane & 3;
    int bm = blockIdx.x * 128, bn = blockIdx.y * 128;

    float acc[4][4][4];
#pragma unroll
    for (int i = 0; i < 4; i++)
#pragma unroll
        for (int j = 0; j < 4; j++)
#pragma unroll
            for (int r = 0; r < 4; r++) acc[i][j][r] = 0.0f;

    // cp.async staging: thread -> row tid/2, 2x16B at half-col (tid&1)*16
    int r0 = tid >> 1;
    int hc = (tid & 1) << 4;                 // 0 or 16 halves
    unsigned base = smem_u32(sh);
    unsigned aDst = base + (unsigned)r0 * (LDRH * 2) + hc * 2;
    unsigned bDst = aDst + OPSTG;
    const __half* aSrc = A + (size_t)(bm + r0) * lda + hc;
    const __half* bSrc = Bm + (size_t)(bn + r0) * ldb + hc;

    // ldmatrix per-lane addresses (stage 0, ks 0); b16 8x8 rows = 16B
    int mi = lane >> 3, lr = lane & 7;
    unsigned aAddr[4], bAddr[2];
#pragma unroll
    for (int mt = 0; mt < 4; mt++)
        aAddr[mt] = base + (unsigned)(wm + mt * 16 + (mi & 1) * 8 + lr) * (LDRH * 2)
                  + (mi >> 1) * 16;
#pragma unroll
    for (int p = 0; p < 2; p++)
        bAddr[p] = base + OPSTG
                 + (unsigned)(wn + (p * 2 + (mi >> 1)) * 8 + lr) * (LDRH * 2)
                 + (mi & 1) * 16;

    auto stage_load = [&](int t, int T) {
        if (t < T) {
            unsigned so = (unsigned)(t % STAGES) * STAGE_BYTES;
            int k0 = t * BKH;
            cp_async16(aDst + so,      aSrc + k0);
            cp_async16(aDst + so + 16, aSrc + k0 + 8);
            cp_async16(bDst + so,      bSrc + k0);
            cp_async16(bDst + so + 16, bSrc + k0 + 8);
        }
        asm volatile("cp.async.commit_group;");
    };

    int T = K / BKH;
    stage_load(0, T);
    stage_load(1, T);

    int s = 0;
    for (int t = 0; t < T; t++) {
        asm volatile("cp.async.wait_group 1;");
        __syncthreads();
        stage_load(t + 2, T);

        unsigned so = (unsigned)s * STAGE_BYTES;
#pragma unroll
        for (int ks = 0; ks < 2; ks++) {
            unsigned kofs = so + ks * 32;    // 16 halves per k16 step
            unsigned afr[4][4], bfr[4][2];
#pragma unroll
            for (int mt = 0; mt < 4; mt++)
                ldsm_x4(afr[mt][0], afr[mt][1], afr[mt][2], afr[mt][3],
                        aAddr[mt] + kofs);
            ldsm_x4(bfr[0][0], bfr[0][1], bfr[1][0], bfr[1][1], bAddr[0] + kofs);
            ldsm_x4(bfr[2][0], bfr[2][1], bfr[3][0], bfr[3][1], bAddr[1] + kofs);
#pragma unroll
            for (int mt = 0; mt < 4; mt++)
#pragma unroll
                for (int nt = 0; nt < 4; nt++)
                    mma_f16(acc[mt][nt], afr[mt], bfr[nt]);
        }
        if (++s >= STAGES) s = 0;
    }

    // ---------------- epilogue ----------------
    float a2v = 0.0f;
    if (EPI == 7) a2v = 0.5f * (*alphap);

#pragma unroll
    for (int mt = 0; mt < 4; mt++) {
#pragma unroll
        for (int half = 0; half < 2; half++) {
            int m = bm + wm + mt * 16 + g + half * 8;
            float rinv = 0.0f;
            if (EPI == 5) rinv = 1.0f / rsum[m];
            float rs = 0.0f;
#pragma unroll
            for (int nt = 0; nt < 4; nt++) {
                int c = bn + wn + nt * 8 + tg * 2;
                float v0 = acc[mt][nt][half * 2];
                float v1 = acc[mt][nt][half * 2 + 1];
                if (EPI == 1) { v0 += bias[c]; v1 += bias[c + 1]; }
                if (EPI == 2) { v0 = tanhf(v0); v1 = tanhf(v1); }
                if (EPI == 3) {
                    v0 += bias[c]; v1 += bias[c + 1];
                    v0 = 0.5f * v0 * (1.0f + erff(v0 * 0.70710678118654752f));
                    v1 = 0.5f * v1 * (1.0f + erff(v1 * 0.70710678118654752f));
                }
                if (EPI == 4) {
                    const float2 rr = *(const float2*)(res + (size_t)m * ldc + c);
                    v0 += bias[c] + rr.x; v1 += bias[c + 1] + rr.y;
                }
                if (EPI == 5) {
                    const float2 rr = *(const float2*)(res + (size_t)m * ldc + c);
                    v0 = v0 * rinv + rr.x; v1 = v1 * rinv + rr.y;
                }
                if (EPI == 6) { v0 = fast_exp(v0 * scale); v1 = fast_exp(v1 * scale); rs += v0 + v1; }
                if (EPI == 7) { v0 = fast_exp(fmaf(v0, a2v, a2v)); v1 = fast_exp(fmaf(v1, a2v, a2v)); }
                if constexpr (OUTH) {
                    *(__half2*)(C + (size_t)m * ldc + c) = __floats2half2_rn(v0, v1);
                } else {
                    float2 o; o.x = v0; o.y = v1;
                    *(float2*)(C + (size_t)m * ldc + c) = o;
                }
            }
            if (EPI == 6) {
                rs += __shfl_xor_sync(0xffffffffu, rs, 1);
                rs += __shfl_xor_sync(0xffffffffu, rs, 2);
                if (tg == 0) atomicAdd(&ssum[m], rs);
            }
        }
    }
}

// --------- blend: u = (mean_h softmax_h + 1e-6) * pcexp; rowsum --------------
// 256 threads x 8 cols = 2048 = SEQ: exactly one vector iteration per thread.
__global__ void __launch_bounds__(256) blend_kernel(
    const __half* __restrict__ scoresE, const float* __restrict__ ssum,
    const __half* __restrict__ pcexp, __half* __restrict__ blend,
    float* __restrict__ rowsum)
{
    __shared__ float sm[8];
    __shared__ float sinvl[NH];
    int b = blockIdx.x / SEQ;
    int i = blockIdx.x - b * SEQ;
    if (threadIdx.x < NH)
        sinvl[threadIdx.x] = 1.0f / (ssum[(b * NH + threadIdx.x) * SEQ + i] * (float)NH);
    __syncthreads();

    int j = threadIdx.x * 8;
    const __half* ebase = scoresE + (((size_t)(b * NH)) * SEQ + i) * SEQ + j;
    float w[8];
#pragma unroll
    for (int q = 0; q < 8; q++) w[q] = 1e-6f;
#pragma unroll
    for (int h = 0; h < NH; h++) {
        uint4 ev = *(const uint4*)(ebase + (size_t)h * SEQ * SEQ);
        const __half2* eh = (const __half2*)&ev;
        float sl = sinvl[h];
#pragma unroll
        for (int q = 0; q < 4; q++) {
            float2 f = __half22float2(eh[q]);
            w[2*q]   = fmaf(f.x, sl, w[2*q]);
            w[2*q+1] = fmaf(f.y, sl, w[2*q+1]);
        }
    }
    uint4 pv = *(const uint4*)(pcexp + ((size_t)b * SEQ + i) * SEQ + j);
    const __half2* ph = (const __half2*)&pv;
    __half2 ov[4];
    float lsum = 0.0f;
#pragma unroll
    for (int q = 0; q < 4; q++) {
        float2 p = __half22float2(ph[q]);
        float u0 = w[2*q] * p.x, u1 = w[2*q+1] * p.y;
        ov[q] = __floats2half2_rn(u0, u1);
        lsum += u0 + u1;
    }
    *(uint4*)(blend + ((size_t)b * SEQ + i) * SEQ + j) = *(uint4*)ov;
    lsum = blockReduceSum256(lsum, sm);
    if (threadIdx.x == 0) rowsum[blockIdx.x] = lsum;
}

// ---------------------------------------------------------------------------
extern "C" void kernel_launch(void* const* d_in, const int* in_sizes, int n_in,
                              void* d_out, int out_size)
{
    const float* x        = (const float*)d_in[0];
    const float* ln1_w    = (const float*)d_in[1];
    const float* ln1_b    = (const float*)d_in[2];
    const float* in_w     = (const float*)d_in[3];
    const float* in_b     = (const float*)d_in[4];
    const float* phase_w  = (const float*)d_in[5];
    const float* alpha    = (const float*)d_in[6];
    const float* ff_w1    = (const float*)d_in[7];
    const float* ff_b1    = (const float*)d_in[8];
    const float* ff_w2    = (const float*)d_in[9];
    const float* ff_b2    = (const float*)d_in[10];
    const float* ln2_w    = (const float*)d_in[11];
    const float* ln2_b    = (const float*)d_in[12];
    float* out            = (float*)d_out;

    __half *xn, *xnT, *qk, *phw, *phase, *scores, *pcv, *blend, *x2, *hbuf,
           *inw, *w1, *w2;
    float *ssum, *rowsum, *xmid;
    cudaGetSymbolAddress((void**)&xn,     g_xn);
    cudaGetSymbolAddress((void**)&xnT,    g_xnT);
    cudaGetSymbolAddress((void**)&qk,     g_qk);
    cudaGetSymbolAddress((void**)&phw,    g_phw);
    cudaGetSymbolAddress((void**)&phase,  g_phase);
    cudaGetSymbolAddress((void**)&scores, g_scores);
    cudaGetSymbolAddress((void**)&ssum,   g_ssum);
    cudaGetSymbolAddress((void**)&pcv,    g_pc);
    cudaGetSymbolAddress((void**)&blend,  g_blend);
    cudaGetSymbolAddress((void**)&rowsum, g_rowsum);
    cudaGetSymbolAddress((void**)&xmid,   g_xmid);
    cudaGetSymbolAddress((void**)&x2,     g_x2);
    cudaGetSymbolAddress((void**)&hbuf,   g_hbuf);
    cudaGetSymbolAddress((void**)&inw,    g_inw);
    cudaGetSymbolAddress((void**)&w1,     g_w1);
    cudaGetSymbolAddress((void**)&w2,     g_w2);

    cudaFuncSetAttribute(tgemm<1>, cudaFuncAttributeMaxDynamicSharedMemorySize, SMEM_DYN);
    cudaFuncSetAttribute(tgemm<2>, cudaFuncAttributeMaxDynamicSharedMemorySize, SMEM_DYN);
    cudaFuncSetAttribute(tgemm<3>, cudaFuncAttributeMaxDynamicSharedMemorySize, SMEM_DYN);
    cudaFuncSetAttribute(tgemm<4>, cudaFuncAttributeMaxDynamicSharedMemorySize, SMEM_DYN);
    cudaFuncSetAttribute(tgemm<5>, cudaFuncAttributeMaxDynamicSharedMemorySize, SMEM_DYN);
    cudaFuncSetAttribute(tgemm<6>, cudaFuncAttributeMaxDynamicSharedMemorySize, SMEM_DYN);
    cudaFuncSetAttribute(tgemm<7>, cudaFuncAttributeMaxDynamicSharedMemorySize, SMEM_DYN);

    // 0) fp16 round-to-nearest weight copies
    half_copy_kernel<<<(2*DIM*DIM + 255)/256, 256>>>(in_w, inw, 2*DIM*DIM);
    half_copy_kernel<<<(FFD*DIM + 255)/256, 256>>>(ff_w1, w1, FFD*DIM);
    half_copy_kernel<<<(DIM*FFD + 255)/256, 256>>>(ff_w2, w2, DIM*FFD);

    // 1) xn = LN1(x) -> fp16; xnT; zero per-head sums; pad+round phase_w
    ln_kernel<<<NROW, 256>>>(x, ln1_w, ln1_b, xn);
    zero_kernel<<<(BB*NH*SEQ + 255)/256, 256>>>(ssum, BB*NH*SEQ);
    pad_phw_kernel<<<(PDPAD*DIM + 255)/256, 256>>>(phase_w, phw);
    transpose_kernel<<<dim3(SEQ/32, DIM/32, BB), 256>>>(xn, xnT);

    // 2) qk = xn @ W[0:1536]^T + b -> fp16   [4096, 1536]
    tgemm<1><<<dim3(NROW/128, 1536/128, 1), 256, SMEM_DYN>>>(
        xn, inw, qk, NROW, 2*DIM, DIM, DIM, DIM, 2*DIM,
        1, 0,0, 0,0, 0,0, 1.0f, in_b, nullptr, 0, nullptr, 0, nullptr, nullptr);

    // 3) phase = tanh(xn @ phw^T) -> fp16    [4096, 128] (cols 64..127 = 0)
    tgemm<2><<<dim3(NROW/128, 1, 1), 256, SMEM_DYN>>>(
        xn, phw, phase, NROW, PDPAD, DIM, DIM, DIM, PDPAD,
        1, 0,0, 0,0, 0,0, 1.0f, nullptr, nullptr, 0, nullptr, 0, nullptr, nullptr);

    // 4) scores e = exp(0.125 * q@k^T) -> fp16 + atomic rowsums  24x[2048,2048]
    tgemm<6><<<dim3(SEQ/128, SEQ/128, BB*NH), 256, SMEM_DYN>>>(
        qk, qk + DIM, scores, SEQ, SEQ, DHD, 2*DIM, 2*DIM, SEQ,
        NH, (long)SEQ*2*DIM, (long)DHD, (long)SEQ*2*DIM, (long)DHD,
            (long)NH*SEQ*SEQ, (long)SEQ*SEQ,
        0.125f, nullptr, nullptr, 0, nullptr, 0, nullptr, ssum);

    // 5) pcexp = exp(0.5*a*(phase@phase^T) + 0.5*a) -> fp16  2x[2048,2048]
    tgemm<7><<<dim3(SEQ/128, SEQ/128, BB), 256, SMEM_DYN>>>(
        phase, phase, pcv, SEQ, SEQ, PDPAD, PDPAD, PDPAD, SEQ,
        1, (long)SEQ*PDPAD, 0, (long)SEQ*PDPAD, 0, (long)SEQ*SEQ, 0,
        1.0f, nullptr, nullptr, 0, nullptr, 0, alpha, nullptr);

    // 6) blend weights (fp16) + row sums
    blend_kernel<<<BB*SEQ, 256>>>(scores, ssum, pcv, blend, rowsum);

    // 7) xmid = x + (blend/rowsum) @ xnT^T -> fp32   2x[2048, 768], K=2048
    tgemm<5><<<dim3(SEQ/128, DIM/128, BB), 256, SMEM_DYN>>>(
        blend, xnT, xmid, SEQ, DIM, SEQ, SEQ, SEQ, DIM,
        1, (long)SEQ*SEQ, 0, (long)DIM*SEQ, 0, (long)SEQ*DIM, 0,
        1.0f, nullptr, x, (long)SEQ*DIM, rowsum, (long)SEQ, nullptr, nullptr);

    // 8) x2 = LN2(xmid) -> fp16
    ln_kernel<<<NROW, 256>>>(xmid, ln2_w, ln2_b, x2);

    // 9) h = gelu(x2 @ ff_w1^T + b1) -> fp16  [4096, 3072]
    tgemm<3><<<dim3(NROW/128, FFD/128, 1), 256, SMEM_DYN>>>(
        x2, w1, hbuf, NROW, FFD, DIM, DIM, DIM, FFD,
        1, 0,0, 0,0, 0,0, 1.0f, ff_b1, nullptr, 0, nullptr, 0, nullptr, nullptr);

    // 10) out = xmid + h @ ff_w2^T + b2 -> fp32  [4096, 768], K=3072
    tgemm<4><<<dim3(NROW/128, DIM/128, 1), 256, SMEM_DYN>>>(
        hbuf, w2, out, NROW, DIM, FFD, FFD, FFD, DIM,
        1, 0,0, 0,0, 0,0, 1.0f, ff_b2, xmid, 0, nullptr, 0, nullptr, nullptr);

    (void)in_sizes; (void)n_in; (void)out_size;
}

// round 10
// speedup vs baseline: 1.9567x; 1.0938x over previous
#include <cuda_runtime.h>
#include <cuda_fp16.h>
#include <math.h>

// Problem dims (fixed by the reference)
#define BB   2
#define SEQ  2048
#define DIM  768
#define NH   12
#define DHD  64
#define FFD  3072
#define PDIM 64
#define PDPAD 128
#define NROW (BB*SEQ)      // 4096

#define STAGES 4
#define BKH    32                        // k-tile in halves
#define LDRH   40                        // padded row length in halves (80 B)
#define OPSTG  (128*LDRH*2)              // 10240 B per operand per stage
#define STAGE_BYTES (2*OPSTG)            // 20480
#define SMEM_DYN (STAGES*STAGE_BYTES)    // 81920

#define LOG2E 1.4426950408889634f

// ---------------- scratch (device globals; no cudaMalloc allowed) ----------
__device__ __align__(16) __half g_xn[NROW*DIM];
__device__ __align__(16) __half g_xnT[NROW*DIM];                  // [B][D][S]
__device__ __align__(16) __half g_qk[NROW*2*DIM];
__device__ __align__(16) __half g_phw[PDPAD*DIM];
__device__ __align__(16) __half g_phase[NROW*PDPAD];
__device__ __align__(16) __half g_scores[(size_t)BB*NH*SEQ*SEQ]; // exp(s/8) fp16
__device__              float  g_ssum[BB*NH*SEQ];
__device__ __align__(16) __half g_pc[(size_t)BB*SEQ*SEQ];        // exp(a*(pc+1)/2)
__device__ __align__(16) __half g_blend[(size_t)BB*SEQ*SEQ];
__device__              float  g_rowsum[BB*SEQ];
__device__ __align__(16) float  g_xmid[NROW*DIM];                // residual: fp32
__device__ __align__(16) __half g_x2[NROW*DIM];
__device__ __align__(16) __half g_hbuf[NROW*FFD];
// fp16-rounded weight copies
__device__ __align__(16) __half g_inw[2*DIM*DIM];
__device__ __align__(16) __half g_w1[FFD*DIM];
__device__ __align__(16) __half g_w2[DIM*FFD];

// ---------------- helpers ----------------------------------------------------
__device__ __forceinline__ float warpReduceSum(float v) {
#pragma unroll
    for (int o = 16; o > 0; o >>= 1) v += __shfl_xor_sync(0xffffffffu, v, o);
    return v;
}
__device__ __forceinline__ float blockReduceSum256(float v, float* sm) {
    v = warpReduceSum(v);
    if ((threadIdx.x & 31) == 0) sm[threadIdx.x >> 5] = v;
    __syncthreads();
    if (threadIdx.x < 32) {
        float t = (threadIdx.x < 8) ? sm[threadIdx.x] : 0.0f;
        t = warpReduceSum(t);
        if (threadIdx.x == 0) sm[0] = t;
    }
    __syncthreads();
    float r = sm[0];
    __syncthreads();
    return r;
}

// exp via MUFU EX2: x assumed scaled by LOG2E already. rel err ~2.4e-7.
__device__ __forceinline__ float ex2f(float x) {
    float r;
    asm("ex2.approx.f32 %0, %1;" : "=f"(r) : "f"(x));
    return r;
}

__device__ __forceinline__ unsigned smem_u32(const void* p) {
    unsigned a;
    asm("{ .reg .u64 t; cvta.to.shared.u64 t, %1; cvt.u32.u64 %0, t; }"
        : "=r"(a) : "l"(p));
    return a;
}
__device__ __forceinline__ void cp_async16(unsigned dst, const void* src) {
    asm volatile("cp.async.cg.shared.global [%0], [%1], 16;" :: "r"(dst), "l"(src));
}
__device__ __forceinline__ void ldsm_x4(unsigned& r0, unsigned& r1,
                                        unsigned& r2, unsigned& r3, unsigned addr) {
    asm volatile("ldmatrix.sync.aligned.m8n8.x4.shared.b16 {%0,%1,%2,%3}, [%4];"
        : "=r"(r0), "=r"(r1), "=r"(r2), "=r"(r3) : "r"(addr));
}
__device__ __forceinline__ void mma_f16(float* c, const unsigned* a, const unsigned* b) {
    asm("mma.sync.aligned.m16n8k16.row.col.f32.f16.f16.f32 "
        "{%0,%1,%2,%3}, {%4,%5,%6,%7}, {%8,%9}, {%0,%1,%2,%3};"
        : "+f"(c[0]), "+f"(c[1]), "+f"(c[2]), "+f"(c[3])
        : "r"(a[0]), "r"(a[1]), "r"(a[2]), "r"(a[3]), "r"(b[0]), "r"(b[1]));
}

// ---------------- LayerNorm: fp32 in, fp16 out -------------------------------
__global__ void __launch_bounds__(256) ln_kernel(
    const float* __restrict__ x, const float* __restrict__ w,
    const float* __restrict__ b, __half* __restrict__ o)
{
    __shared__ float sm[8];
    const float* xr = x + (size_t)blockIdx.x * DIM;
    int t = threadIdx.x;
    float v0 = xr[t], v1 = xr[t + 256], v2 = xr[t + 512];
    float mean = blockReduceSum256(v0 + v1 + v2, sm) * (1.0f / DIM);
    float d0 = v0 - mean, d1 = v1 - mean, d2 = v2 - mean;
    float var = blockReduceSum256(d0*d0 + d1*d1 + d2*d2, sm) * (1.0f / DIM);
    float r = rsqrtf(var + 1e-5f);
    __half* orow = o + (size_t)blockIdx.x * DIM;
    orow[t      ] = __float2half_rn(d0 * r * w[t      ] + b[t      ]);
    orow[t + 256] = __float2half_rn(d1 * r * w[t + 256] + b[t + 256]);
    orow[t + 512] = __float2half_rn(d2 * r * w[t + 512] + b[t + 512]);
}

__global__ void __launch_bounds__(256) zero_kernel(float* __restrict__ p, int n) {
    int i = blockIdx.x * 256 + threadIdx.x;
    if (i < n) p[i] = 0.0f;
}

__global__ void __launch_bounds__(256) half_copy_kernel(
    const float* __restrict__ in, __half* __restrict__ o, int n)
{
    int i = blockIdx.x * 256 + threadIdx.x;
    if (i < n) o[i] = __float2half_rn(in[i]);
}

// pad phase_w [64,768] -> [128,768] with zeros, fp16
__global__ void __launch_bounds__(256) pad_phw_kernel(
    const float* __restrict__ w, __half* __restrict__ o)
{
    int i = blockIdx.x * 256 + threadIdx.x;
    if (i < PDPAD * DIM) o[i] = __float2half_rn((i < PDIM * DIM) ? w[i] : 0.0f);
}

// transpose per batch: in [SEQ][DIM] -> out [DIM][SEQ]  (fp16)
__global__ void __launch_bounds__(256) transpose_kernel(
    const __half* __restrict__ in, __half* __restrict__ out)
{
    __shared__ __half t[32][33];
    int b = blockIdx.z;
    const __half* ib = in + (size_t)b * SEQ * DIM;
    __half* ob = out + (size_t)b * SEQ * DIM;
    int tx = threadIdx.x & 31, ty = threadIdx.x >> 5;
    int sbase = blockIdx.x * 32;
    int dbase = blockIdx.y * 32;
#pragma unroll
    for (int i = 0; i < 32; i += 8)
        t[ty + i][tx] = ib[(size_t)(sbase + ty + i) * DIM + dbase + tx];
    __syncthreads();
#pragma unroll
    for (int i = 0; i < 32; i += 8)
        ob[(size_t)(dbase + ty + i) * SEQ + sbase + tx] = t[tx][ty + i];
}

// ============================================================================
// fp16 tensor-core GEMM: 128x128x32 CTA tile, 8 warps (2x4), warp 64x32,
// mma.sync m16n8k16 (f32 accum), 4-stage cp.async pipeline, ldmatrix.x4.
// A [M,K] half row-major, B [N,K] half row-major: C = A @ B^T.
// EPI: 1=+bias->h, 2=tanh->h, 3=bias+GELU->h, 4=bias+residual->f,
//      5=row-divide(rowsum)+residual->f, 6=ex2(scale*v)->h + atomic rowsum
//        (scale pre-multiplied by log2e), 7=ex2(a2l*v + a2l)->h, a2l=0.5*alpha*log2e
// ============================================================================
template<int EPI> struct OutT { using T = __half; };
template<> struct OutT<4> { using T = float; };
template<> struct OutT<5> { using T = float; };

template<int EPI>
__global__ void __launch_bounds__(256, 2) tgemm(
    const __half* __restrict__ A, const __half* __restrict__ Bm,
    typename OutT<EPI>::T* __restrict__ C,
    int M, int N, int K, int lda, int ldb, int ldc,
    int zdiv,
    long as1, long as2, long bs1, long bs2, long cs1, long cs2,
    float scale,
    const float* __restrict__ bias,
    const float* __restrict__ res, long ress1,
    const float* __restrict__ rsum, long rsums1,
    const float* __restrict__ alphap,
    float* __restrict__ ssum)
{
    constexpr bool OUTH = (EPI != 4 && EPI != 5);
    extern __shared__ char sh[];

    int z = blockIdx.z;
    int z1 = z / zdiv, z2 = z - z1 * zdiv;
    A  += z1 * as1 + z2 * as2;
    Bm += z1 * bs1 + z2 * bs2;
    C  += z1 * cs1 + z2 * cs2;
    if (EPI == 4 || EPI == 5) res  += z1 * ress1;
    if (EPI == 5)             rsum += z1 * rsums1;
    if (EPI == 6)             ssum += (size_t)z * M;

    int tid  = threadIdx.x;
    int lane = tid & 31;
    int wid  = tid >> 5;
    int wm   = (wid & 1) * 64;
    int wn   = (wid >> 1) * 32;
    int g    = lane >> 2;
    int tg   = lane & 3;
    int bm = blockIdx.x * 128, bn = blockIdx.y * 128;

    float acc[4][4][4];
#pragma unroll
    for (int i = 0; i < 4; i++)
#pragma unroll
        for (int j = 0; j < 4; j++)
#pragma unroll
            for (int r = 0; r < 4; r++) acc[i][j][r] = 0.0f;

    // cp.async staging: thread -> row tid/2, 2x16B at half-col (tid&1)*16
    int r0 = tid >> 1;
    int hc = (tid & 1) << 4;                 // 0 or 16 halves
    unsigned base = smem_u32(sh);
    unsigned aDst = base + (unsigned)r0 * (LDRH * 2) + hc * 2;
    unsigned bDst = aDst + OPSTG;
    const __half* aSrc = A + (size_t)(bm + r0) * lda + hc;
    const __half* bSrc = Bm + (size_t)(bn + r0) * ldb + hc;

    // ldmatrix per-lane addresses (stage 0, ks 0); b16 8x8 rows = 16B
    int mi = lane >> 3, lr = lane & 7;
    unsigned aAddr[4], bAddr[2];
#pragma unroll
    for (int mt = 0; mt < 4; mt++)
        aAddr[mt] = base + (unsigned)(wm + mt * 16 + (mi & 1) * 8 + lr) * (LDRH * 2)
                  + (mi >> 1) * 16;
#pragma unroll
    for (int p = 0; p < 2; p++)
        bAddr[p] = base + OPSTG
                 + (unsigned)(wn + (p * 2 + (mi >> 1)) * 8 + lr) * (LDRH * 2)
                 + (mi & 1) * 16;

    auto stage_load = [&](int t, int T) {
        if (t < T) {
            unsigned so = (unsigned)(t % STAGES) * STAGE_BYTES;
            int k0 = t * BKH;
            cp_async16(aDst + so,      aSrc + k0);
            cp_async16(aDst + so + 16, aSrc + k0 + 8);
            cp_async16(bDst + so,      bSrc + k0);
            cp_async16(bDst + so + 16, bSrc + k0 + 8);
        }
        asm volatile("cp.async.commit_group;");
    };

    int T = K / BKH;
    stage_load(0, T);
    stage_load(1, T);
    stage_load(2, T);

    int s = 0;
    for (int t = 0; t < T; t++) {
        asm volatile("cp.async.wait_group 2;");
        __syncthreads();
        stage_load(t + 3, T);

        unsigned so = (unsigned)s * STAGE_BYTES;
#pragma unroll
        for (int ks = 0; ks < 2; ks++) {
            unsigned kofs = so + ks * 32;    // 16 halves per k16 step
            unsigned afr[4][4], bfr[4][2];
#pragma unroll
            for (int mt = 0; mt < 4; mt++)
                ldsm_x4(afr[mt][0], afr[mt][1], afr[mt][2], afr[mt][3],
                        aAddr[mt] + kofs);
            ldsm_x4(bfr[0][0], bfr[0][1], bfr[1][0], bfr[1][1], bAddr[0] + kofs);
            ldsm_x4(bfr[2][0], bfr[2][1], bfr[3][0], bfr[3][1], bAddr[1] + kofs);
#pragma unroll
            for (int mt = 0; mt < 4; mt++)
#pragma unroll
                for (int nt = 0; nt < 4; nt++)
                    mma_f16(acc[mt][nt], afr[mt], bfr[nt]);
        }
        if (++s >= STAGES) s = 0;
    }

    // ---------------- epilogue ----------------
    float a2v = 0.0f;
    if (EPI == 7) a2v = 0.5f * (*alphap) * LOG2E;

#pragma unroll
    for (int mt = 0; mt < 4; mt++) {
#pragma unroll
        for (int half = 0; half < 2; half++) {
            int m = bm + wm + mt * 16 + g + half * 8;
            float rinv = 0.0f;
            if (EPI == 5) rinv = 1.0f / rsum[m];
            float rs = 0.0f;
#pragma unroll
            for (int nt = 0; nt < 4; nt++) {
                int c = bn + wn + nt * 8 + tg * 2;
                float v0 = acc[mt][nt][half * 2];
                float v1 = acc[mt][nt][half * 2 + 1];
                if (EPI == 1) { v0 += bias[c]; v1 += bias[c + 1]; }
                if (EPI == 2) { v0 = tanhf(v0); v1 = tanhf(v1); }
                if (EPI == 3) {
                    v0 += bias[c]; v1 += bias[c + 1];
                    v0 = 0.5f * v0 * (1.0f + erff(v0 * 0.70710678118654752f));
                    v1 = 0.5f * v1 * (1.0f + erff(v1 * 0.70710678118654752f));
                }
                if (EPI == 4) {
                    const float2 rr = *(const float2*)(res + (size_t)m * ldc + c);
                    v0 += bias[c] + rr.x; v1 += bias[c + 1] + rr.y;
                }
                if (EPI == 5) {
                    const float2 rr = *(const float2*)(res + (size_t)m * ldc + c);
                    v0 = v0 * rinv + rr.x; v1 = v1 * rinv + rr.y;
                }
                if (EPI == 6) { v0 = ex2f(v0 * scale); v1 = ex2f(v1 * scale); rs += v0 + v1; }
                if (EPI == 7) { v0 = ex2f(fmaf(v0, a2v, a2v)); v1 = ex2f(fmaf(v1, a2v, a2v)); }
                if constexpr (OUTH) {
                    *(__half2*)(C + (size_t)m * ldc + c) = __floats2half2_rn(v0, v1);
                } else {
                    float2 o; o.x = v0; o.y = v1;
                    *(float2*)(C + (size_t)m * ldc + c) = o;
                }
            }
            if (EPI == 6) {
                rs += __shfl_xor_sync(0xffffffffu, rs, 1);
                rs += __shfl_xor_sync(0xffffffffu, rs, 2);
                if (tg == 0) atomicAdd(&ssum[m], rs);
            }
        }
    }
}

// --------- blend: u = (mean_h softmax_h + 1e-6) * pcexp; rowsum --------------
// 256 threads x 8 cols = 2048 = SEQ: exactly one vector iteration per thread.
__global__ void __launch_bounds__(256) blend_kernel(
    const __half* __restrict__ scoresE, const float* __restrict__ ssum,
    const __half* __restrict__ pcexp, __half* __restrict__ blend,
    float* __restrict__ rowsum)
{
    __shared__ float sm[8];
    __shared__ float sinvl[NH];
    int b = blockIdx.x / SEQ;
    int i = blockIdx.x - b * SEQ;
    if (threadIdx.x < NH)
        sinvl[threadIdx.x] = 1.0f / (ssum[(b * NH + threadIdx.x) * SEQ + i] * (float)NH);
    __syncthreads();

    int j = threadIdx.x * 8;
    const __half* ebase = scoresE + (((size_t)(b * NH)) * SEQ + i) * SEQ + j;
    float w[8];
#pragma unroll
    for (int q = 0; q < 8; q++) w[q] = 1e-6f;
#pragma unroll
    for (int h = 0; h < NH; h++) {
        uint4 ev = *(const uint4*)(ebase + (size_t)h * SEQ * SEQ);
        const __half2* eh = (const __half2*)&ev;
        float sl = sinvl[h];
#pragma unroll
        for (int q = 0; q < 4; q++) {
            float2 f = __half22float2(eh[q]);
            w[2*q]   = fmaf(f.x, sl, w[2*q]);
            w[2*q+1] = fmaf(f.y, sl, w[2*q+1]);
        }
    }
    uint4 pv = *(const uint4*)(pcexp + ((size_t)b * SEQ + i) * SEQ + j);
    const __half2* ph = (const __half2*)&pv;
    __half2 ov[4];
    float lsum = 0.0f;
#pragma unroll
    for (int q = 0; q < 4; q++) {
        float2 p = __half22float2(ph[q]);
        float u0 = w[2*q] * p.x, u1 = w[2*q+1] * p.y;
        ov[q] = __floats2half2_rn(u0, u1);
        lsum += u0 + u1;
    }
    *(uint4*)(blend + ((size_t)b * SEQ + i) * SEQ + j) = *(uint4*)ov;
    lsum = blockReduceSum256(lsum, sm);
    if (threadIdx.x == 0) rowsum[blockIdx.x] = lsum;
}

// ---------------------------------------------------------------------------
extern "C" void kernel_launch(void* const* d_in, const int* in_sizes, int n_in,
                              void* d_out, int out_size)
{
    const float* x        = (const float*)d_in[0];
    const float* ln1_w    = (const float*)d_in[1];
    const float* ln1_b    = (const float*)d_in[2];
    const float* in_w     = (const float*)d_in[3];
    const float* in_b     = (const float*)d_in[4];
    const float* phase_w  = (const float*)d_in[5];
    const float* alpha    = (const float*)d_in[6];
    const float* ff_w1    = (const float*)d_in[7];
    const float* ff_b1    = (const float*)d_in[8];
    const float* ff_w2    = (const float*)d_in[9];
    const float* ff_b2    = (const float*)d_in[10];
    const float* ln2_w    = (const float*)d_in[11];
    const float* ln2_b    = (const float*)d_in[12];
    float* out            = (float*)d_out;

    __half *xn, *xnT, *qk, *phw, *phase, *scores, *pcv, *blend, *x2, *hbuf,
           *inw, *w1, *w2;
    float *ssum, *rowsum, *xmid;
    cudaGetSymbolAddress((void**)&xn,     g_xn);
    cudaGetSymbolAddress((void**)&xnT,    g_xnT);
    cudaGetSymbolAddress((void**)&qk,     g_qk);
    cudaGetSymbolAddress((void**)&phw,    g_phw);
    cudaGetSymbolAddress((void**)&phase,  g_phase);
    cudaGetSymbolAddress((void**)&scores, g_scores);
    cudaGetSymbolAddress((void**)&ssum,   g_ssum);
    cudaGetSymbolAddress((void**)&pcv,    g_pc);
    cudaGetSymbolAddress((void**)&blend,  g_blend);
    cudaGetSymbolAddress((void**)&rowsum, g_rowsum);
    cudaGetSymbolAddress((void**)&xmid,   g_xmid);
    cudaGetSymbolAddress((void**)&x2,     g_x2);
    cudaGetSymbolAddress((void**)&hbuf,   g_hbuf);
    cudaGetSymbolAddress((void**)&inw,    g_inw);
    cudaGetSymbolAddress((void**)&w1,     g_w1);
    cudaGetSymbolAddress((void**)&w2,     g_w2);

    cudaFuncSetAttribute(tgemm<1>, cudaFuncAttributeMaxDynamicSharedMemorySize, SMEM_DYN);
    cudaFuncSetAttribute(tgemm<2>, cudaFuncAttributeMaxDynamicSharedMemorySize, SMEM_DYN);
    cudaFuncSetAttribute(tgemm<3>, cudaFuncAttributeMaxDynamicSharedMemorySize, SMEM_DYN);
    cudaFuncSetAttribute(tgemm<4>, cudaFuncAttributeMaxDynamicSharedMemorySize, SMEM_DYN);
    cudaFuncSetAttribute(tgemm<5>, cudaFuncAttributeMaxDynamicSharedMemorySize, SMEM_DYN);
    cudaFuncSetAttribute(tgemm<6>, cudaFuncAttributeMaxDynamicSharedMemorySize, SMEM_DYN);
    cudaFuncSetAttribute(tgemm<7>, cudaFuncAttributeMaxDynamicSharedMemorySize, SMEM_DYN);

    // 0) fp16 round-to-nearest weight copies
    half_copy_kernel<<<(2*DIM*DIM + 255)/256, 256>>>(in_w, inw, 2*DIM*DIM);
    half_copy_kernel<<<(FFD*DIM + 255)/256, 256>>>(ff_w1, w1, FFD*DIM);
    half_copy_kernel<<<(DIM*FFD + 255)/256, 256>>>(ff_w2, w2, DIM*FFD);

    // 1) xn = LN1(x) -> fp16; xnT; zero per-head sums; pad+round phase_w
    ln_kernel<<<NROW, 256>>>(x, ln1_w, ln1_b, xn);
    zero_kernel<<<(BB*NH*SEQ + 255)/256, 256>>>(ssum, BB*NH*SEQ);
    pad_phw_kernel<<<(PDPAD*DIM + 255)/256, 256>>>(phase_w, phw);
    transpose_kernel<<<dim3(SEQ/32, DIM/32, BB), 256>>>(xn, xnT);

    // 2) qk = xn @ W[0:1536]^T + b -> fp16   [4096, 1536]
    tgemm<1><<<dim3(NROW/128, 1536/128, 1), 256, SMEM_DYN>>>(
        xn, inw, qk, NROW, 2*DIM, DIM, DIM, DIM, 2*DIM,
        1, 0,0, 0,0, 0,0, 1.0f, in_b, nullptr, 0, nullptr, 0, nullptr, nullptr);

    // 3) phase = tanh(xn @ phw^T) -> fp16    [4096, 128] (cols 64..127 = 0)
    tgemm<2><<<dim3(NROW/128, 1, 1), 256, SMEM_DYN>>>(
        xn, phw, phase, NROW, PDPAD, DIM, DIM, DIM, PDPAD,
        1, 0,0, 0,0, 0,0, 1.0f, nullptr, nullptr, 0, nullptr, 0, nullptr, nullptr);

    // 4) scores e = ex2(log2e/8 * q@k^T) -> fp16 + atomic rowsums  24x[2048,2048]
    tgemm<6><<<dim3(SEQ/128, SEQ/128, BB*NH), 256, SMEM_DYN>>>(
        qk, qk + DIM, scores, SEQ, SEQ, DHD, 2*DIM, 2*DIM, SEQ,
        NH, (long)SEQ*2*DIM, (long)DHD, (long)SEQ*2*DIM, (long)DHD,
            (long)NH*SEQ*SEQ, (long)SEQ*SEQ,
        0.125f * LOG2E, nullptr, nullptr, 0, nullptr, 0, nullptr, ssum);

    // 5) pcexp = ex2(a2l*(phase@phase^T) + a2l) -> fp16  2x[2048,2048], K=64
    tgemm<7><<<dim3(SEQ/128, SEQ/128, BB), 256, SMEM_DYN>>>(
        phase, phase, pcv, SEQ, SEQ, PDIM, PDPAD, PDPAD, SEQ,
        1, (long)SEQ*PDPAD, 0, (long)SEQ*PDPAD, 0, (long)SEQ*SEQ, 0,
        1.0f, nullptr, nullptr, 0, nullptr, 0, alpha, nullptr);

    // 6) blend weights (fp16) + row sums
    blend_kernel<<<BB*SEQ, 256>>>(scores, ssum, pcv, blend, rowsum);

    // 7) xmid = x + (blend/rowsum) @ xnT^T -> fp32   2x[2048, 768], K=2048
    tgemm<5><<<dim3(SEQ/128, DIM/128, BB), 256, SMEM_DYN>>>(
        blend, xnT, xmid, SEQ, DIM, SEQ, SEQ, SEQ, DIM,
        1, (long)SEQ*SEQ, 0, (long)DIM*SEQ, 0, (long)SEQ*DIM, 0,
        1.0f, nullptr, x, (long)SEQ*DIM, rowsum, (long)SEQ, nullptr, nullptr);

    // 8) x2 = LN2(xmid) -> fp16
    ln_kernel<<<NROW, 256>>>(xmid, ln2_w, ln2_b, x2);

    // 9) h = gelu(x2 @ ff_w1^T + b1) -> fp16  [4096, 3072]
    tgemm<3><<<dim3(NROW/128, FFD/128, 1), 256, SMEM_DYN>>>(
        x2, w1, hbuf, NROW, FFD, DIM, DIM, DIM, FFD,
        1, 0,0, 0,0, 0,0, 1.0f, ff_b1, nullptr, 0, nullptr, 0, nullptr, nullptr);

    // 10) out = xmid + h @ ff_w2^T + b2 -> fp32  [4096, 768], K=3072
    tgemm<4><<<dim3(NROW/128, DIM/128, 1), 256, SMEM_DYN>>>(
        hbuf, w2, out, NROW, DIM, FFD, FFD, FFD, DIM,
        1, 0,0, 0,0, 0,0, 1.0f, ff_b2, xmid, 0, nullptr, 0, nullptr, nullptr);

    (void)in_sizes; (void)n_in; (void)out_size;
}